// round 2
// baseline (speedup 1.0000x reference)
#include <cuda_runtime.h>

// LSTM persistent kernel, fp32, packed f32x2 FFMA (zero-MOV inner loop).
// L=512 sequential steps; 128 co-resident CTAs (256 thr each), one device-wide
// barrier per step. Each CTA owns 8 h-columns (x4 gates = 32 gate columns),
// K = E+H = 1536 fused. c-state persists in smem; h ping-pongs through a
// __device__ buffer (read with __ldcg to bypass incoherent L1).

#define Ld   512
#define Bd   64
#define Ed   512
#define Hd   1024
#define EHd  1536
#define NCTA 128
#define NTHR 256
#define KC   32
#define NCH  (EHd / KC)   // 48 chunks
#define HC   8            // h-cols per CTA
#define GC   32           // gate-cols per CTA
#define LBH  (Ld * Bd * Hd)

__device__ float    g_hbuf[2][Bd * Hd];
__device__ unsigned g_bar_count;  // returns to 0 after each barrier (replay-safe)
__device__ unsigned g_bar_gen;    // monotonic across barriers and graph replays

__device__ __forceinline__ unsigned long long dup2(float x) {
    unsigned long long r;
    asm("mov.b64 %0, {%1, %1};" : "=l"(r) : "f"(x));
    return r;
}
__device__ __forceinline__ void ffma2(unsigned long long &d, unsigned long long a, unsigned long long b) {
    asm("fma.rn.f32x2 %0, %1, %2, %0;" : "+l"(d) : "l"(a), "l"(b));
}
__device__ __forceinline__ float2 unpack2(unsigned long long v) {
    float2 f;
    asm("mov.b64 {%0, %1}, %2;" : "=f"(f.x), "=f"(f.y) : "l"(v));
    return f;
}

// Sense-reversing grid barrier; all NCTA blocks are co-resident (128 CTAs,
// 256 thr, ~44KB smem -> 1 CTA/SM on 148 SMs, single wave guaranteed).
__device__ __forceinline__ void grid_barrier() {
    __threadfence();
    __syncthreads();
    if (threadIdx.x == 0) {
        unsigned gen = *(volatile unsigned *)&g_bar_gen;
        unsigned arrived = atomicAdd(&g_bar_count, 1u);
        if (arrived == NCTA - 1) {
            atomicExch(&g_bar_count, 0u);
            __threadfence();
            atomicAdd(&g_bar_gen, 1u);
        } else {
            while (*(volatile unsigned *)&g_bar_gen == gen) { __nanosleep(32); }
        }
        __threadfence();
    }
    __syncthreads();
}

__global__ void __launch_bounds__(NTHR, 1) lstm_persistent(
    const float *__restrict__ x,  const float *__restrict__ c0, const float *__restrict__ h0,
    const float *__restrict__ Wf, const float *__restrict__ bf,
    const float *__restrict__ Wi, const float *__restrict__ bi,
    const float *__restrict__ Wg, const float *__restrict__ bg,
    const float *__restrict__ Wo, const float *__restrict__ bo,
    float *__restrict__ out)
{
    // A chunk transposed: Asm[kk][b], stride 66 floats (264B: 8B-aligned rows,
    // conflict-free LDS.64). W chunk stored PRE-DUPLICATED as {w,w} pairs so the
    // inner loop needs no packing MOVs.
    __shared__ float              Asm[2][KC][66];
    __shared__ unsigned long long Wsm2[2][KC][GC];
    __shared__ float              Zsm[Bd][33];     // gate pre-activations
    __shared__ float              Csm[Bd * HC];    // persistent c-state
    __shared__ float              Bsm[GC];         // biases

    const int tid   = threadIdx.x;
    const int ci    = blockIdx.x;
    const int col0h = ci * HC;

    // W staging role: thread -> (wkk, gate, half). One float4 per chunk.
    const int wkk   = tid >> 3;
    const int wq    = tid & 7;
    const int wg_   = wq >> 1;
    const int whalf = wq & 1;
    const float *wbase = (wg_ == 0) ? Wf : (wg_ == 1) ? Wi : (wg_ == 2) ? Wg : Wo;
    const int wc0 = wg_ * 8 + whalf * 4;

    // compute role: 2 rows x 4 gate-cols per thread.
    const int cgrp = tid & 7;        // col group (cols cgrp*4 .. +3)
    const int rgrp = tid >> 3;       // 0..31
    const int r0   = rgrp * 2;
    const int cc0  = cgrp * 4;

    if (tid < GC) {
        int g = tid >> 3, jj = tid & 7;
        const float *bp = (g == 0) ? bf : (g == 1) ? bi : (g == 2) ? bg : bo;
        Bsm[tid] = bp[col0h + jj];
    }
#pragma unroll
    for (int q = 0; q < 2; ++q) {
        int lin = q * NTHR + tid;
        int b = lin >> 3, jj = lin & 7;
        Csm[lin] = c0[b * Hd + col0h + jj];
    }
    __syncthreads();

    for (int t = 0; t < Ld; ++t) {
        const float *hsrc = (t == 0) ? h0 : g_hbuf[(t - 1) & 1];
        const float *xt   = x + (size_t)t * (Bd * Ed);

        unsigned long long acc[4];
#pragma unroll
        for (int p = 0; p < 4; ++p) acc[p] = 0ull;

        float4 aP[2];
        float4 wP;

        // ---- prologue: load + store chunk 0 (entirely within x: KC < Ed) ----
        {
#pragma unroll
            for (int u = 0; u < 2; ++u) {
                int lin = u * NTHR + tid;
                int b = lin >> 3, kq = lin & 7;
                aP[u] = __ldg((const float4 *)(xt + b * Ed + kq * 4));
            }
            wP = __ldg((const float4 *)(wbase + (size_t)wkk * Hd + col0h + whalf * 4));
#pragma unroll
            for (int u = 0; u < 2; ++u) {
                int lin = u * NTHR + tid;
                int b = lin >> 3, kq = lin & 7;
                Asm[0][kq * 4 + 0][b] = aP[u].x;
                Asm[0][kq * 4 + 1][b] = aP[u].y;
                Asm[0][kq * 4 + 2][b] = aP[u].z;
                Asm[0][kq * 4 + 3][b] = aP[u].w;
            }
            ulonglong2 w01; w01.x = dup2(wP.x); w01.y = dup2(wP.y);
            ulonglong2 w23; w23.x = dup2(wP.z); w23.y = dup2(wP.w);
            *(ulonglong2 *)&Wsm2[0][wkk][wc0]     = w01;
            *(ulonglong2 *)&Wsm2[0][wkk][wc0 + 2] = w23;
        }

        // ---- pipelined K loop over 48 chunks ----
        int s = 0;
        for (int ch = 0; ch < NCH; ++ch) {
            __syncthreads();
            if (ch + 1 < NCH) {
                const int kbase = (ch + 1) * KC;
                if (kbase < Ed) {
#pragma unroll
                    for (int u = 0; u < 2; ++u) {
                        int lin = u * NTHR + tid;
                        int b = lin >> 3, kq = lin & 7;
                        aP[u] = __ldg((const float4 *)(xt + b * Ed + kbase + kq * 4));
                    }
                } else {
                    const int hb = kbase - Ed;
#pragma unroll
                    for (int u = 0; u < 2; ++u) {
                        int lin = u * NTHR + tid;
                        int b = lin >> 3, kq = lin & 7;
                        // L2-only: g_hbuf is written by other SMs; local L1 is stale.
                        aP[u] = __ldcg((const float4 *)(hsrc + b * Hd + hb + kq * 4));
                    }
                }
                wP = __ldg((const float4 *)(wbase + (size_t)(kbase + wkk) * Hd + col0h + whalf * 4));
            }

#pragma unroll 8
            for (int kk = 0; kk < KC; ++kk) {
                unsigned long long a2 = *(const unsigned long long *)&Asm[s][kk][r0];
                ulonglong2 b01 = *(const ulonglong2 *)&Wsm2[s][kk][cc0];
                ulonglong2 b23 = *(const ulonglong2 *)&Wsm2[s][kk][cc0 + 2];
                ffma2(acc[0], a2, b01.x);
                ffma2(acc[1], a2, b01.y);
                ffma2(acc[2], a2, b23.x);
                ffma2(acc[3], a2, b23.y);
            }

            if (ch + 1 < NCH) {
                const int sn = s ^ 1;
#pragma unroll
                for (int u = 0; u < 2; ++u) {
                    int lin = u * NTHR + tid;
                    int b = lin >> 3, kq = lin & 7;
                    Asm[sn][kq * 4 + 0][b] = aP[u].x;
                    Asm[sn][kq * 4 + 1][b] = aP[u].y;
                    Asm[sn][kq * 4 + 2][b] = aP[u].z;
                    Asm[sn][kq * 4 + 3][b] = aP[u].w;
                }
                ulonglong2 w01; w01.x = dup2(wP.x); w01.y = dup2(wP.y);
                ulonglong2 w23; w23.x = dup2(wP.z); w23.y = dup2(wP.w);
                *(ulonglong2 *)&Wsm2[sn][wkk][wc0]     = w01;
                *(ulonglong2 *)&Wsm2[sn][wkk][wc0 + 2] = w23;
            }
            s ^= 1;
        }

        // ---- scatter z to smem for the gate exchange ----
#pragma unroll
        for (int p = 0; p < 4; ++p) {
            float2 v = unpack2(acc[p]);           // {z[r0][c], z[r0+1][c]}
            Zsm[r0][cc0 + p]     = v.x;
            Zsm[r0 + 1][cc0 + p] = v.y;
        }
        __syncthreads();

        // ---- elementwise LSTM cell + outputs ----
        const int wbuf = t & 1;
        float *cb  = out + (size_t)t * (Bd * Hd);
        float *hb2 = out + (size_t)LBH + (size_t)t * (Bd * Hd);
#pragma unroll
        for (int q = 0; q < 2; ++q) {
            int lin = q * NTHR + tid;
            int b = lin >> 3, jj = lin & 7;
            float zf = Zsm[b][jj]      + Bsm[jj];
            float zi = Zsm[b][8 + jj]  + Bsm[8 + jj];
            float zg = Zsm[b][16 + jj] + Bsm[16 + jj];
            float zo = Zsm[b][24 + jj] + Bsm[24 + jj];
            float fg = 1.f / (1.f + __expf(-zf));
            float ig = 1.f / (1.f + __expf(-zi));
            float gg = tanhf(zg);
            float og = 1.f / (1.f + __expf(-zo));
            float cn = Csm[lin] * fg + ig * gg;
            float hn = og * tanhf(cn);
            Csm[lin] = cn;
            int j = col0h + jj;
            cb[b * Hd + j]  = cn;
            hb2[b * Hd + j] = hn;
            g_hbuf[wbuf][b * Hd + j] = hn;
        }

        if (t + 1 < Ld) grid_barrier();
    }
}

extern "C" void kernel_launch(void* const* d_in, const int* in_sizes, int n_in,
                              void* d_out, int out_size) {
    (void)in_sizes; (void)n_in; (void)out_size;
    const float *x  = (const float *)d_in[0];
    const float *c0 = (const float *)d_in[1];
    const float *h0 = (const float *)d_in[2];
    const float *Wf = (const float *)d_in[3];
    const float *bf = (const float *)d_in[4];
    const float *Wi = (const float *)d_in[5];
    const float *bi = (const float *)d_in[6];
    const float *Wg = (const float *)d_in[7];
    const float *bg = (const float *)d_in[8];
    const float *Wo = (const float *)d_in[9];
    const float *bo = (const float *)d_in[10];
    float *out = (float *)d_out;

    lstm_persistent<<<NCTA, NTHR>>>(x, c0, h0, Wf, bf, Wi, bi, Wg, bg, Wo, bo, out);
}

// round 5
// speedup vs baseline: 1.9983x; 1.9983x over previous
#include <cuda_runtime.h>

// LSTM persistent kernel, fp32, packed f32x2 FFMA, broadcast-optimized tiles.
// 128 co-resident CTAs x 128 threads; each CTA owns 8 h-cols (32 gate-cols).
// Thread tile 4 rows x 4 cols; A stored row-duplicated {a,a} in smem so the
// inner loop is 3 conflict-free LDS + 8 FFMA2 per k (fma-pipe bound).
// c-state persists in smem; h ping-pongs through a __device__ buffer (__ldcg).

#define Ld   512
#define Bd   64
#define Ed   512
#define Hd   1024
#define EHd  1536
#define NCTA 128
#define NTHR 128
#define KC   64
#define NCH  (EHd / KC)   // 24 chunks
#define HC   8            // h-cols per CTA
#define GC   32           // gate-cols per CTA
#define LBH  (Ld * Bd * Hd)

// A rows padded to 66 u64 (528B, 16B-aligned rows). W rows padded to 36 floats
// (144B, 16B-aligned). Z rows 34 floats (136B, 8B-aligned).
struct SmemLayout {
    unsigned long long A[2][KC][66];   // duplicated pairs {a,a}, [k][row]
    float              W[2][KC][36];   // plain, [k][gatecol]
    float              Z[Bd][34];
    float              C[Bd * HC];
    float              Bb[GC];
};

__device__ float    g_hbuf[2][Bd * Hd];
__device__ unsigned g_bar_count;   // returns to 0 after each barrier (replay-safe)
__device__ unsigned g_bar_gen;     // monotonic across barriers and replays

__device__ __forceinline__ unsigned long long dup2(float x) {
    unsigned long long r;
    asm("mov.b64 %0, {%1, %1};" : "=l"(r) : "f"(x));
    return r;
}
__device__ __forceinline__ void ffma2(unsigned long long &d, unsigned long long a, unsigned long long b) {
    asm("fma.rn.f32x2 %0, %1, %2, %0;" : "+l"(d) : "l"(a), "l"(b));
}
__device__ __forceinline__ float2 unpack2(unsigned long long v) {
    float2 f;
    asm("mov.b64 {%0, %1}, %2;" : "=f"(f.x), "=f"(f.y) : "l"(v));
    return f;
}

// Sense-reversing grid barrier; 128 CTAs on 148 SMs -> single wave guaranteed.
__device__ __forceinline__ void grid_barrier() {
    __threadfence();
    __syncthreads();
    if (threadIdx.x == 0) {
        unsigned gen = *(volatile unsigned *)&g_bar_gen;
        unsigned arrived = atomicAdd(&g_bar_count, 1u);
        if (arrived == NCTA - 1) {
            atomicExch(&g_bar_count, 0u);
            __threadfence();
            atomicAdd(&g_bar_gen, 1u);
        } else {
            while (*(volatile unsigned *)&g_bar_gen == gen) { __nanosleep(32); }
        }
        __threadfence();
    }
    __syncthreads();
}

__global__ void __launch_bounds__(NTHR, 1) lstm_persistent(
    const float *__restrict__ x,  const float *__restrict__ c0, const float *__restrict__ h0,
    const float *__restrict__ Wf, const float *__restrict__ bf,
    const float *__restrict__ Wi, const float *__restrict__ bi,
    const float *__restrict__ Wg, const float *__restrict__ bg,
    const float *__restrict__ Wo, const float *__restrict__ bo,
    float *__restrict__ out)
{
    extern __shared__ char smem_raw[];
    SmemLayout &S = *(SmemLayout *)smem_raw;

    const int tid   = threadIdx.x;
    const int ci    = blockIdx.x;
    const int col0h = ci * HC;

    // ---- compute role: lane = rg*8 + cg; thread tile rows [arow..arow+3],
    //      cols [cc0..cc0+3] ----
    const int warp = tid >> 5;
    const int lane = tid & 31;
    const int rg   = lane >> 3;          // 0..3
    const int cg   = lane & 7;           // 0..7
    const int arow = warp * 16 + rg * 4; // row base (0..60)
    const int cc0  = cg * 4;             // col base (0..28)

    // ---- W staging role: wq fixed per thread; 4 k-rows per pass ----
    const int wq    = tid & 7;           // gate*2 + half
    const int wg_   = wq >> 1;
    const int whalf = wq & 1;
    const float *wbase = (wg_ == 0) ? Wf : (wg_ == 1) ? Wi : (wg_ == 2) ? Wg : Wo;
    const int wc0 = wq * 4;              // = gate*8 + half*4, dest col in Wsm

    if (tid < GC) {
        int g = tid >> 3, jj = tid & 7;
        const float *bp = (g == 0) ? bf : (g == 1) ? bi : (g == 2) ? bg : bo;
        S.Bb[tid] = bp[col0h + jj];
    }
#pragma unroll
    for (int q = 0; q < 4; ++q) {
        int lin = q * NTHR + tid;
        int b = lin >> 3, jj = lin & 7;
        S.C[lin] = c0[b * Hd + col0h + jj];
    }
    __syncthreads();

    for (int t = 0; t < Ld; ++t) {
        const float *hsrc = (t == 0) ? h0 : g_hbuf[(t - 1) & 1];
        const float *xt   = x + (size_t)t * (Bd * Ed);

        unsigned long long acc[8];       // acc[r*2+cp] = {z[arow+r][cc0+2cp], z[..][cc0+2cp+1]}
#pragma unroll
        for (int p = 0; p < 8; ++p) acc[p] = 0ull;

        float4 aP[8];
        float4 wP[4];

        // ---- prologue: load + store chunk 0 (entirely in x: KC=64 < Ed) ----
        {
#pragma unroll
            for (int u = 0; u < 8; ++u) {
                int lin = u * NTHR + tid;
                int b = lin & 63, kq = lin >> 6;       // kq 0..15
                aP[u] = __ldg((const float4 *)(xt + b * Ed + kq * 4));
            }
#pragma unroll
            for (int u = 0; u < 4; ++u) {
                int wkk = u * 16 + (tid >> 3);
                wP[u] = __ldg((const float4 *)(wbase + (size_t)wkk * Hd + col0h + whalf * 4));
            }
#pragma unroll
            for (int u = 0; u < 8; ++u) {
                int lin = u * NTHR + tid;
                int b = lin & 63, kq = lin >> 6;
                S.A[0][kq * 4 + 0][b] = dup2(aP[u].x);
                S.A[0][kq * 4 + 1][b] = dup2(aP[u].y);
                S.A[0][kq * 4 + 2][b] = dup2(aP[u].z);
                S.A[0][kq * 4 + 3][b] = dup2(aP[u].w);
            }
#pragma unroll
            for (int u = 0; u < 4; ++u) {
                int wkk = u * 16 + (tid >> 3);
                *(float4 *)&S.W[0][wkk][wc0] = wP[u];
            }
        }

        // ---- pipelined K loop over 24 chunks ----
        int s = 0;
        for (int ch = 0; ch < NCH; ++ch) {
            __syncthreads();
            if (ch + 1 < NCH) {
                const int kbase = (ch + 1) * KC;
                if (kbase < Ed) {
#pragma unroll
                    for (int u = 0; u < 8; ++u) {
                        int lin = u * NTHR + tid;
                        int b = lin & 63, kq = lin >> 6;
                        aP[u] = __ldg((const float4 *)(xt + b * Ed + kbase + kq * 4));
                    }
                } else {
                    const int hb = kbase - Ed;
#pragma unroll
                    for (int u = 0; u < 8; ++u) {
                        int lin = u * NTHR + tid;
                        int b = lin & 63, kq = lin >> 6;
                        // L2-only: g_hbuf is written by other SMs; local L1 is stale.
                        aP[u] = __ldcg((const float4 *)(hsrc + b * Hd + hb + kq * 4));
                    }
                }
#pragma unroll
                for (int u = 0; u < 4; ++u) {
                    int wkk = u * 16 + (tid >> 3);
                    wP[u] = __ldg((const float4 *)(wbase + (size_t)(kbase + wkk) * Hd + col0h + whalf * 4));
                }
            }

            {
                const unsigned long long *Ab = &S.A[s][0][0];
                const float *Wb = &S.W[s][0][0];
#pragma unroll 8
                for (int kk = 0; kk < KC; ++kk) {
                    ulonglong2 aLo = *(const ulonglong2 *)(Ab + kk * 66 + arow);
                    ulonglong2 aHi = *(const ulonglong2 *)(Ab + kk * 66 + arow + 2);
                    ulonglong2 wp  = *(const ulonglong2 *)(Wb + kk * 36 + cc0);
                    ffma2(acc[0], aLo.x, wp.x);
                    ffma2(acc[1], aLo.x, wp.y);
                    ffma2(acc[2], aLo.y, wp.x);
                    ffma2(acc[3], aLo.y, wp.y);
                    ffma2(acc[4], aHi.x, wp.x);
                    ffma2(acc[5], aHi.x, wp.y);
                    ffma2(acc[6], aHi.y, wp.x);
                    ffma2(acc[7], aHi.y, wp.y);
                }
            }

            if (ch + 1 < NCH) {
                const int sn = s ^ 1;
#pragma unroll
                for (int u = 0; u < 8; ++u) {
                    int lin = u * NTHR + tid;
                    int b = lin & 63, kq = lin >> 6;
                    S.A[sn][kq * 4 + 0][b] = dup2(aP[u].x);
                    S.A[sn][kq * 4 + 1][b] = dup2(aP[u].y);
                    S.A[sn][kq * 4 + 2][b] = dup2(aP[u].z);
                    S.A[sn][kq * 4 + 3][b] = dup2(aP[u].w);
                }
#pragma unroll
                for (int u = 0; u < 4; ++u) {
                    int wkk = u * 16 + (tid >> 3);
                    *(float4 *)&S.W[sn][wkk][wc0] = wP[u];
                }
            }
            s ^= 1;
        }

        // ---- scatter z to smem for the gate exchange ----
#pragma unroll
        for (int r = 0; r < 4; ++r) {
            float2 v0 = unpack2(acc[r * 2 + 0]);
            float2 v1 = unpack2(acc[r * 2 + 1]);
            *(float2 *)&S.Z[arow + r][cc0]     = v0;
            *(float2 *)&S.Z[arow + r][cc0 + 2] = v1;
        }
        __syncthreads();

        // ---- elementwise LSTM cell + outputs ----
        const int wbuf = t & 1;
        float *cb  = out + (size_t)t * (Bd * Hd);
        float *hb2 = out + (size_t)LBH + (size_t)t * (Bd * Hd);
#pragma unroll
        for (int q = 0; q < 4; ++q) {
            int lin = q * NTHR + tid;
            int b = lin >> 3, jj = lin & 7;
            float zf = S.Z[b][jj]      + S.Bb[jj];
            float zi = S.Z[b][8 + jj]  + S.Bb[8 + jj];
            float zg = S.Z[b][16 + jj] + S.Bb[16 + jj];
            float zo = S.Z[b][24 + jj] + S.Bb[24 + jj];
            float fg = 1.f / (1.f + __expf(-zf));
            float ig = 1.f / (1.f + __expf(-zi));
            float gg = tanhf(zg);
            float og = 1.f / (1.f + __expf(-zo));
            float cn = S.C[lin] * fg + ig * gg;
            float hn = og * tanhf(cn);
            S.C[lin] = cn;
            int j = col0h + jj;
            cb[b * Hd + j]  = cn;
            hb2[b * Hd + j] = hn;
            g_hbuf[wbuf][b * Hd + j] = hn;
        }

        if (t + 1 < Ld) grid_barrier();
    }
}

extern "C" void kernel_launch(void* const* d_in, const int* in_sizes, int n_in,
                              void* d_out, int out_size) {
    (void)in_sizes; (void)n_in; (void)out_size;
    const float *x  = (const float *)d_in[0];
    const float *c0 = (const float *)d_in[1];
    const float *h0 = (const float *)d_in[2];
    const float *Wf = (const float *)d_in[3];
    const float *bf = (const float *)d_in[4];
    const float *Wi = (const float *)d_in[5];
    const float *bi = (const float *)d_in[6];
    const float *Wg = (const float *)d_in[7];
    const float *bg = (const float *)d_in[8];
    const float *Wo = (const float *)d_in[9];
    const float *bo = (const float *)d_in[10];
    float *out = (float *)d_out;

    static int smem_set = 0;
    if (!smem_set) {
        cudaFuncSetAttribute(lstm_persistent,
                             cudaFuncAttributeMaxDynamicSharedMemorySize,
                             (int)sizeof(SmemLayout));
        smem_set = 1;
    }
    lstm_persistent<<<NCTA, NTHR, sizeof(SmemLayout)>>>(
        x, c0, h0, Wf, bf, Wi, bi, Wg, bg, Wo, bo, out);
}